// round 1
// baseline (speedup 1.0000x reference)
#include <cuda_runtime.h>
#include <math.h>

// Problem constants
#define B_  64
#define N_  1024          // H*W = 32*32
#define D_  512
#define K_  64
#define EPS_ 1e-12f

// Scratch (allocation-free rule: __device__ globals)
__device__ float g_a[B_ * N_ * K_];      // 16 MB soft-assignments
__device__ float g_vkd[B_ * K_ * D_];    // 8 MB  VLAD accumulators
__device__ float g_asum[B_ * K_];
__device__ float g_invrow[B_ * K_];
__device__ float g_ginv[B_];

// ---------------------------------------------------------------------------
// Kernel A: s = x @ w  (per 64-pixel tile), fused softmax over K=64 -> g_a
// block: 256 threads (tx = cluster group 0..15, ty = pixel group 0..15)
// each thread: 4 pixels x 4 clusters
// ---------------------------------------------------------------------------
__global__ __launch_bounds__(256) void assign_kernel(
    const float* __restrict__ x, const float* __restrict__ w)
{
    __shared__ float xs[64 * 36];   // 64 pixels x 32 d, pad to 36
    __shared__ float ws[32 * 64];   // 32 d x 64 k

    const int t  = threadIdx.x;
    const int tx = t & 15;
    const int ty = t >> 4;
    const int pix0 = blockIdx.x * 64;
    const float* xbase = x + (size_t)pix0 * D_;

    float acc[4][4];
#pragma unroll
    for (int i = 0; i < 4; i++)
#pragma unroll
        for (int j = 0; j < 4; j++) acc[i][j] = 0.f;

    for (int dc = 0; dc < D_; dc += 32) {
        // load x tile: 64 rows x 32 floats = 512 float4
#pragma unroll
        for (int r = 0; r < 2; r++) {
            int idx = t + r * 256;            // float4 index
            int row = idx >> 3, c4 = idx & 7;
            float4 v = *(const float4*)(xbase + (size_t)row * D_ + dc + c4 * 4);
            *(float4*)(xs + row * 36 + c4 * 4) = v;
        }
        // load w tile: 32 rows x 64 floats = 512 float4
#pragma unroll
        for (int r = 0; r < 2; r++) {
            int idx = t + r * 256;
            int row = idx >> 4, c4 = idx & 15;
            *(float4*)(ws + row * 64 + c4 * 4) =
                *(const float4*)(w + (size_t)(dc + row) * K_ + c4 * 4);
        }
        __syncthreads();

#pragma unroll
        for (int d = 0; d < 32; d++) {
            float4 wv = *(const float4*)(ws + d * 64 + tx * 4);
            float x0 = xs[(ty * 4 + 0) * 36 + d];
            float x1 = xs[(ty * 4 + 1) * 36 + d];
            float x2 = xs[(ty * 4 + 2) * 36 + d];
            float x3 = xs[(ty * 4 + 3) * 36 + d];
            acc[0][0] += x0 * wv.x; acc[0][1] += x0 * wv.y; acc[0][2] += x0 * wv.z; acc[0][3] += x0 * wv.w;
            acc[1][0] += x1 * wv.x; acc[1][1] += x1 * wv.y; acc[1][2] += x1 * wv.z; acc[1][3] += x1 * wv.w;
            acc[2][0] += x2 * wv.x; acc[2][1] += x2 * wv.y; acc[2][2] += x2 * wv.z; acc[2][3] += x2 * wv.w;
            acc[3][0] += x3 * wv.x; acc[3][1] += x3 * wv.y; acc[3][2] += x3 * wv.z; acc[3][3] += x3 * wv.w;
        }
        __syncthreads();
    }

    // softmax across K=64: each pixel's scores live in the 16 tx-lanes
    // (lanes with the same ty are contiguous half-warps -> width-16 shuffles)
#pragma unroll
    for (int i = 0; i < 4; i++) {
        float m = fmaxf(fmaxf(acc[i][0], acc[i][1]), fmaxf(acc[i][2], acc[i][3]));
#pragma unroll
        for (int off = 8; off; off >>= 1)
            m = fmaxf(m, __shfl_xor_sync(0xffffffffu, m, off, 16));
        float e0 = expf(acc[i][0] - m);
        float e1 = expf(acc[i][1] - m);
        float e2 = expf(acc[i][2] - m);
        float e3 = expf(acc[i][3] - m);
        float s = e0 + e1 + e2 + e3;
#pragma unroll
        for (int off = 8; off; off >>= 1)
            s += __shfl_xor_sync(0xffffffffu, s, off, 16);
        float inv = 1.0f / s;
        int pix = pix0 + ty * 4 + i;
        float4 o = make_float4(e0 * inv, e1 * inv, e2 * inv, e3 * inv);
        *(float4*)(g_a + (size_t)pix * K_ + tx * 4) = o;
    }
}

// ---------------------------------------------------------------------------
// Kernel B: vkd[b,k,d] = sum_n a[b,n,k] * x[b,n,d]
// grid: (4 d-tiles of 128, 64 batches), block 256 (tx=d group, ty=k group)
// thread micro-tile: 4 k x 8 d
// ---------------------------------------------------------------------------
__global__ __launch_bounds__(256) void vlad_kernel(const float* __restrict__ x)
{
    __shared__ float as_[16 * 64];    // 16 n x 64 k
    __shared__ float xsb[16 * 128];   // 16 n x 128 d

    const int b  = blockIdx.y;
    const int d0 = blockIdx.x * 128;
    const int t  = threadIdx.x;
    const int tx = t & 15;
    const int ty = t >> 4;

    const float* ab = g_a + (size_t)b * N_ * K_;
    const float* xb = x  + (size_t)b * N_ * D_;

    float acc[4][8];
#pragma unroll
    for (int i = 0; i < 4; i++)
#pragma unroll
        for (int j = 0; j < 8; j++) acc[i][j] = 0.f;

    for (int n0 = 0; n0 < N_; n0 += 16) {
        {   // a tile: 16x64 = 256 float4, 1 per thread
            int row = t >> 4, c4 = t & 15;
            *(float4*)(as_ + row * 64 + c4 * 4) =
                *(const float4*)(ab + (size_t)(n0 + row) * K_ + c4 * 4);
        }
#pragma unroll
        for (int r = 0; r < 2; r++) {  // x tile: 16x128 = 512 float4
            int idx = t + r * 256;
            int row = idx >> 5, c4 = idx & 31;
            *(float4*)(xsb + row * 128 + c4 * 4) =
                *(const float4*)(xb + (size_t)(n0 + row) * D_ + d0 + c4 * 4);
        }
        __syncthreads();

#pragma unroll
        for (int n = 0; n < 16; n++) {
            float4 av  = *(const float4*)(as_ + n * 64 + ty * 4);
            float4 xv0 = *(const float4*)(xsb + n * 128 + tx * 8);
            float4 xv1 = *(const float4*)(xsb + n * 128 + tx * 8 + 4);
            float ar[4] = {av.x, av.y, av.z, av.w};
            float xr[8] = {xv0.x, xv0.y, xv0.z, xv0.w, xv1.x, xv1.y, xv1.z, xv1.w};
#pragma unroll
            for (int i = 0; i < 4; i++)
#pragma unroll
                for (int j = 0; j < 8; j++)
                    acc[i][j] += ar[i] * xr[j];
        }
        __syncthreads();
    }

#pragma unroll
    for (int i = 0; i < 4; i++) {
        size_t base = (size_t)b * (K_ * D_) + (size_t)(ty * 4 + i) * D_ + d0 + tx * 8;
        *(float4*)(g_vkd + base)     = make_float4(acc[i][0], acc[i][1], acc[i][2], acc[i][3]);
        *(float4*)(g_vkd + base + 4) = make_float4(acc[i][4], acc[i][5], acc[i][6], acc[i][7]);
    }
}

// ---------------------------------------------------------------------------
// Kernel C1: per batch: asum[b,k], row norms S_k of (vkd + asum*C^T),
//            inv-row norms, global inverse norm
// ---------------------------------------------------------------------------
__global__ __launch_bounds__(256) void norm_kernel(const float* __restrict__ Cm)
{
    __shared__ float s_part[256];
    __shared__ float s_asum[64];
    __shared__ float s_S[64];

    const int b = blockIdx.x;
    const int t = threadIdx.x;

    // asum[b,k] = sum_n a[b,n,k]  (deterministic tree, coalesced)
    {
        int k = t & 63, rg = t >> 6;   // 4 row groups
        float acc = 0.f;
        const float* ab = g_a + (size_t)b * N_ * K_;
        for (int n = rg; n < N_; n += 4)
            acc += ab[(size_t)n * K_ + k];
        s_part[t] = acc;
    }
    __syncthreads();
    if (t < 64) {
        float s = s_part[t] + s_part[t + 64] + s_part[t + 128] + s_part[t + 192];
        s_asum[t] = s;
        g_asum[b * K_ + t] = s;
    }
    __syncthreads();

    // S_k: one warp per k (8 warps -> 8 iterations)
    const int warp = t >> 5, lane = t & 31;
    for (int kk = warp; kk < K_; kk += 8) {
        float asv = s_asum[kk];
        const float* vrow = g_vkd + (size_t)b * (K_ * D_) + (size_t)kk * D_;
        float s = 0.f;
        for (int d = lane; d < D_; d += 32) {
            float v = vrow[d] + asv * Cm[(size_t)d * K_ + kk];
            s += v * v;
        }
#pragma unroll
        for (int off = 16; off; off >>= 1)
            s += __shfl_xor_sync(0xffffffffu, s, off);
        if (lane == 0) s_S[kk] = s;
    }
    __syncthreads();

    if (t < 64) g_invrow[b * K_ + t] = rsqrtf(s_S[t] + EPS_);
    if (t == 0) {
        float g = 0.f;
        for (int i = 0; i < 64; i++) g += s_S[i] / (s_S[i] + EPS_);
        g_ginv[b] = rsqrtf(g + EPS_);
    }
}

// ---------------------------------------------------------------------------
// Kernel C2: out[b, d*K + k] = (vkd[b,k,d] + asum*C[d,k]) * invrow * ginv
// grid: (8 d-tiles of 64, 64 batches); 64x64 transpose via smem
// ---------------------------------------------------------------------------
__global__ __launch_bounds__(256) void output_kernel(
    const float* __restrict__ Cm, float* __restrict__ out)
{
    __shared__ float tile[64 * 65];
    __shared__ float s_as[64];
    __shared__ float s_inv[64];

    const int b  = blockIdx.y;
    const int d0 = blockIdx.x * 64;
    const int t  = threadIdx.x;

    if (t < 64) {
        s_as[t]  = g_asum[b * K_ + t];
        s_inv[t] = g_invrow[b * K_ + t];
    }
    const float gi = g_ginv[b];
    const float* vb = g_vkd + (size_t)b * (K_ * D_);

    for (int idx = t; idx < 4096; idx += 256) {
        int kk = idx >> 6, dc = idx & 63;     // coalesced read along d
        tile[kk * 65 + dc] = vb[(size_t)kk * D_ + d0 + dc];
    }
    __syncthreads();

    float* ob = out + (size_t)b * (D_ * K_);
    for (int idx = t; idx < 4096; idx += 256) {
        int dc = idx >> 6, kk = idx & 63;     // coalesced write along k
        float v = (tile[kk * 65 + dc] + s_as[kk] * Cm[(size_t)(d0 + dc) * K_ + kk])
                  * s_inv[kk] * gi;
        ob[(size_t)(d0 + dc) * K_ + kk] = v;
    }
}

// ---------------------------------------------------------------------------
extern "C" void kernel_launch(void* const* d_in, const int* in_sizes, int n_in,
                              void* d_out, int out_size)
{
    const float* x  = (const float*)d_in[0];   // [B,H,W,D]
    const float* w  = (const float*)d_in[1];   // [D,K]
    const float* Cm = (const float*)d_in[2];   // [D,K]
    float* out = (float*)d_out;                // [B, D*K]

    assign_kernel<<<(B_ * N_) / 64, 256>>>(x, w);
    vlad_kernel<<<dim3(D_ / 128, B_), 256>>>(x);
    norm_kernel<<<B_, 256>>>(Cm);
    output_kernel<<<dim3(D_ / 64, B_), 256>>>(Cm, out);
}

// round 3
// speedup vs baseline: 2.6026x; 2.6026x over previous
#include <cuda_runtime.h>
#include <cuda_bf16.h>
#include <stdint.h>
#include <math.h>

#define B_  64
#define N_  1024
#define D_  512
#define K_  64
#define EPS_ 1e-12f

// ---------------- scratch ----------------
__device__ __nv_bfloat16 g_wT_h[K_ * D_];
__device__ __nv_bfloat16 g_wT_l[K_ * D_];
__device__ __nv_bfloat16 g_aT_h[(size_t)B_ * K_ * N_];   // a^T [b][k][n]
__device__ __nv_bfloat16 g_aT_l[(size_t)B_ * K_ * N_];
__device__ float g_asum_part[B_ * 8 * K_];
__device__ float g_S_part[B_ * 4 * K_];
__device__ float g_v[(size_t)B_ * D_ * K_];              // v pre-norm [b][d][k]
__device__ float g_invrow[B_ * K_];
__device__ float g_ginv[B_];

// ---------------- helpers ----------------
__device__ __forceinline__ uint32_t smem_u32(const void* p) {
    uint32_t a;
    asm("{ .reg .u64 t; cvta.to.shared.u64 t, %1; cvt.u32.u64 %0, t; }" : "=r"(a) : "l"(p));
    return a;
}
// swizzle for 128B rows and 256B rows (both reduce to off ^ ((row&7)<<4))
__device__ __forceinline__ uint32_t sw128(uint32_t off) { return off ^ ((off >> 3) & 0x70); }
__device__ __forceinline__ uint32_t sw256(uint32_t off) { return off ^ ((off >> 4) & 0x70); }

__device__ __forceinline__ void ldsm_x4(uint32_t* r, uint32_t a) {
    asm volatile("ldmatrix.sync.aligned.m8n8.x4.shared.b16 {%0,%1,%2,%3}, [%4];"
        : "=r"(r[0]), "=r"(r[1]), "=r"(r[2]), "=r"(r[3]) : "r"(a));
}
__device__ __forceinline__ void ldsm_x4t(uint32_t* r, uint32_t a) {
    asm volatile("ldmatrix.sync.aligned.m8n8.x4.trans.shared.b16 {%0,%1,%2,%3}, [%4];"
        : "=r"(r[0]), "=r"(r[1]), "=r"(r[2]), "=r"(r[3]) : "r"(a));
}
__device__ __forceinline__ void mma16816(float* c, const uint32_t* a, uint32_t b0, uint32_t b1) {
    asm volatile("mma.sync.aligned.m16n8k16.row.col.f32.bf16.bf16.f32 "
        "{%0,%1,%2,%3}, {%4,%5,%6,%7}, {%8,%9}, {%0,%1,%2,%3};"
        : "+f"(c[0]), "+f"(c[1]), "+f"(c[2]), "+f"(c[3])
        : "r"(a[0]), "r"(a[1]), "r"(a[2]), "r"(a[3]), "r"(b0), "r"(b1));
}
__device__ __forceinline__ void sts64(uint32_t addr, uint32_t a, uint32_t b) {
    asm volatile("st.shared.v2.b32 [%0], {%1,%2};" :: "r"(addr), "r"(a), "r"(b) : "memory");
}
__device__ __forceinline__ void sts128(uint32_t addr, uint4 v) {
    asm volatile("st.shared.v4.b32 [%0], {%1,%2,%3,%4};"
        :: "r"(addr), "r"(v.x), "r"(v.y), "r"(v.z), "r"(v.w) : "memory");
}
__device__ __forceinline__ void split2(float a, float b, uint32_t& h, uint32_t& l) {
    __nv_bfloat162 H = __floats2bfloat162_rn(a, b);
    float ra = a - __bfloat162float(H.x);
    float rb = b - __bfloat162float(H.y);
    __nv_bfloat162 L = __floats2bfloat162_rn(ra, rb);
    h = *(uint32_t*)&H; l = *(uint32_t*)&L;
}

// ---------------- kernel 0: w -> wT hi/lo bf16 ----------------
__global__ __launch_bounds__(256) void prep_kernel(const float* __restrict__ w) {
    int e = blockIdx.x * 256 + threadIdx.x;        // 32768 elems
    int k = e >> 9, d = e & 511;
    float v = w[(size_t)d * K_ + k];
    __nv_bfloat16 h = __float2bfloat16(v);
    g_wT_h[(size_t)k * D_ + d] = h;
    g_wT_l[(size_t)k * D_ + d] = __float2bfloat16(v - __bfloat162float(h));
}

// ---------------- kernel 1: s = x@w (HMMA, 3-term bf16) + softmax -> aT ----------------
// CTA: 128 rows (n) x 64 cols (k-cluster). 8 warps, each 16x64.
__global__ __launch_bounds__(256) void gemm1_kernel(const float* __restrict__ x) {
    __shared__ __align__(1024) char smem[49152];
    const uint32_t S0 = smem_u32(smem);
    const uint32_t XH = S0, XL = S0 + 16384, WH = S0 + 32768, WL = S0 + 40960;
    float* stage = (float*)smem;                   // overlay after mainloop: 128x66 f32

    const int t = threadIdx.x, wid = t >> 5, l = t & 31;
    const int bIdx = blockIdx.x >> 3, tile = blockIdx.x & 7;
    const float* xb = x + ((size_t)bIdx * N_ + (size_t)tile * 128) * D_;

    float acc[8][4];
#pragma unroll
    for (int f = 0; f < 8; f++)
#pragma unroll
        for (int j = 0; j < 4; j++) acc[f][j] = 0.f;

    const int rA  = (l & 15);
    const int cA8 = (l >> 4) << 3;
    const int rB  = (l & 7) + ((l >> 4) << 3);
    const int cB8 = ((l >> 3) & 1) << 3;

    for (int c = 0; c < 8; c++) {
        const int d0 = c * 64;
        __syncthreads();
        // x chunk: 128 rows x 64 d (fp32 -> bf16 hi/lo, sw128 smem, 128B rows)
#pragma unroll
        for (int i = 0; i < 8; i++) {
            int e = t + i * 256;                   // 2048 float4
            int r = e >> 4, f4 = e & 15;
            float4 v = *(const float4*)(xb + (size_t)r * D_ + d0 + f4 * 4);
            uint32_t h0, l0, h1, l1;
            split2(v.x, v.y, h0, l0);
            split2(v.z, v.w, h1, l1);
            uint32_t off = sw128((uint32_t)(r * 128 + f4 * 8));
            sts64(XH + off, h0, h1);
            sts64(XL + off, l0, l1);
        }
        // w chunk: 64 rows (k-cluster) x 64 d, already bf16 hi/lo
#pragma unroll
        for (int i = 0; i < 2; i++) {
            int e = t + i * 256;                   // 512 uint4
            int r = e >> 3, u = e & 7;
            uint32_t off = sw128((uint32_t)(r * 128 + u * 16));
            sts128(WH + off, *(const uint4*)((const char*)g_wT_h + ((size_t)r * D_ + d0) * 2 + u * 16));
            sts128(WL + off, *(const uint4*)((const char*)g_wT_l + ((size_t)r * D_ + d0) * 2 + u * 16));
        }
        __syncthreads();
#pragma unroll
        for (int ks = 0; ks < 4; ks++) {
            const int k0 = ks * 16;
            uint32_t offA = sw128((uint32_t)((16 * wid + rA) * 128 + (k0 + cA8) * 2));
            uint32_t ah[4], al[4];
            ldsm_x4(ah, XH + offA);
            ldsm_x4(al, XL + offA);
#pragma unroll
            for (int fp = 0; fp < 4; fp++) {
                uint32_t offB = sw128((uint32_t)((fp * 16 + rB) * 128 + (k0 + cB8) * 2));
                uint32_t bh[4], bl[4];
                ldsm_x4(bh, WH + offB);
                ldsm_x4(bl, WL + offB);
                mma16816(acc[2*fp],   ah, bh[0], bh[1]);
                mma16816(acc[2*fp+1], ah, bh[2], bh[3]);
                mma16816(acc[2*fp],   ah, bl[0], bl[1]);
                mma16816(acc[2*fp+1], ah, bl[2], bl[3]);
                mma16816(acc[2*fp],   al, bh[0], bh[1]);
                mma16816(acc[2*fp+1], al, bh[2], bh[3]);
            }
        }
    }
    __syncthreads();

    // softmax (rows r0 = 16*wid + l/4 and r0+8; full row lives in the 4-lane quad)
    const int q = l >> 2, qq = l & 3;
    const int r0 = 16 * wid + q;
    float m0 = -1e30f, m1 = -1e30f;
#pragma unroll
    for (int f = 0; f < 8; f++) {
        m0 = fmaxf(m0, fmaxf(acc[f][0], acc[f][1]));
        m1 = fmaxf(m1, fmaxf(acc[f][2], acc[f][3]));
    }
    m0 = fmaxf(m0, __shfl_xor_sync(~0u, m0, 1));
    m0 = fmaxf(m0, __shfl_xor_sync(~0u, m0, 2));
    m1 = fmaxf(m1, __shfl_xor_sync(~0u, m1, 1));
    m1 = fmaxf(m1, __shfl_xor_sync(~0u, m1, 2));
    float s0 = 0.f, s1 = 0.f;
#pragma unroll
    for (int f = 0; f < 8; f++) {
        acc[f][0] = __expf(acc[f][0] - m0);
        acc[f][1] = __expf(acc[f][1] - m0);
        acc[f][2] = __expf(acc[f][2] - m1);
        acc[f][3] = __expf(acc[f][3] - m1);
        s0 += acc[f][0] + acc[f][1];
        s1 += acc[f][2] + acc[f][3];
    }
    s0 += __shfl_xor_sync(~0u, s0, 1); s0 += __shfl_xor_sync(~0u, s0, 2);
    s1 += __shfl_xor_sync(~0u, s1, 1); s1 += __shfl_xor_sync(~0u, s1, 2);
    const float i0 = 1.0f / s0, i1 = 1.0f / s1;
#pragma unroll
    for (int f = 0; f < 8; f++) {
        *(float2*)&stage[r0 * 66 + 8 * f + 2 * qq]       = make_float2(acc[f][0] * i0, acc[f][1] * i0);
        *(float2*)&stage[(r0 + 8) * 66 + 8 * f + 2 * qq] = make_float2(acc[f][2] * i1, acc[f][3] * i1);
    }
    __syncthreads();

    // asum partial over this 128-row tile
    if (t < 64) {
        float s = 0.f;
#pragma unroll 8
        for (int r = 0; r < 128; r++) s += stage[r * 66 + t];
        g_asum_part[(bIdx * 8 + tile) * 64 + t] = s;
    }
    // aT hi/lo (transpose through stage)
    const size_t abase = (size_t)bIdx * K_ * N_ + (size_t)tile * 128;
    for (int e = t; e < 64 * 128; e += 256) {
        int k = e >> 7, j = e & 127;
        float a = stage[j * 66 + k];
        __nv_bfloat16 h = __float2bfloat16(a);
        g_aT_h[abase + (size_t)k * N_ + j] = h;
        g_aT_l[abase + (size_t)k * N_ + j] = __float2bfloat16(a - __bfloat162float(h));
    }
}

// ---------------- kernel 2: vT[d,k] = sum_n x[n,d]*a[n,k] (HMMA, trans-A) ----------------
// CTA: 128 d-rows x 64 k-cols per (d-tile, b). 8 warps, each 16x64.
__global__ __launch_bounds__(256) void gemm2_kernel(const float* __restrict__ x,
                                                    const float* __restrict__ Cm) {
    __shared__ __align__(1024) char smem[49152];
    const uint32_t S0 = smem_u32(smem);
    const uint32_t XSH = S0, XSL = S0 + 16384, ATH = S0 + 32768, ATL = S0 + 40960;
    float* s_red  = (float*)smem;          // overlay (post-loop): 8*64 floats
    float* s_asum = (float*)(smem + 2048); // overlay (post-loop): 64 floats

    const int t = threadIdx.x, wid = t >> 5, l = t & 31;
    const int bIdx = blockIdx.y, d0 = blockIdx.x * 128;
    const float* xb = x + (size_t)bIdx * N_ * D_ + d0;
    const __nv_bfloat16* ath = g_aT_h + (size_t)bIdx * K_ * N_;
    const __nv_bfloat16* atl = g_aT_l + (size_t)bIdx * K_ * N_;

    float acc[8][4];
#pragma unroll
    for (int f = 0; f < 8; f++)
#pragma unroll
        for (int j = 0; j < 4; j++) acc[f][j] = 0.f;

    const int rT = (l & 7) + ((l >> 4) << 3);
    const int c8 = ((l >> 3) & 1) << 3;

    for (int c = 0; c < 16; c++) {                 // n chunks of 64
        const int n0 = c * 64;
        __syncthreads();
        // x tile: 64 n-rows x 128 d (fp32 -> bf16 hi/lo, sw256, 256B rows)
#pragma unroll
        for (int i = 0; i < 8; i++) {
            int e = t + i * 256;                   // 2048 float4
            int r = e >> 5, f4 = e & 31;
            float4 v = *(const float4*)(xb + (size_t)(n0 + r) * D_ + f4 * 4);
            uint32_t h0, l0, h1, l1;
            split2(v.x, v.y, h0, l0);
            split2(v.z, v.w, h1, l1);
            uint32_t off = sw256((uint32_t)(r * 256 + f4 * 8));
            sts64(XSH + off, h0, h1);
            sts64(XSL + off, l0, l1);
        }
        // aT tile: 64 k-rows x 64 n, bf16 hi/lo, sw128
#pragma unroll
        for (int i = 0; i < 2; i++) {
            int e = t + i * 256;
            int r = e >> 3, u = e & 7;
            uint32_t off = sw128((uint32_t)(r * 128 + u * 16));
            sts128(ATH + off, *(const uint4*)((const char*)(ath + (size_t)r * N_ + n0) + u * 16));
            sts128(ATL + off, *(const uint4*)((const char*)(atl + (size_t)r * N_ + n0) + u * 16));
        }
        __syncthreads();
#pragma unroll
        for (int ks = 0; ks < 4; ks++) {
            const int nk = ks * 16;
            uint32_t offA = sw256((uint32_t)((nk + rT) * 256 + (16 * wid + c8) * 2));
            uint32_t ah[4], al[4];
            ldsm_x4t(ah, XSH + offA);              // A = x^T via ldmatrix.trans
            ldsm_x4t(al, XSL + offA);
#pragma unroll
            for (int fp = 0; fp < 4; fp++) {
                uint32_t offB = sw128((uint32_t)((fp * 16 + rT) * 128 + (nk + c8) * 2));
                uint32_t bh[4], bl[4];
                ldsm_x4(bh, ATH + offB);
                ldsm_x4(bl, ATL + offB);
                mma16816(acc[2*fp],   ah, bh[0], bh[1]);
                mma16816(acc[2*fp+1], ah, bh[2], bh[3]);
                mma16816(acc[2*fp],   ah, bl[0], bl[1]);
                mma16816(acc[2*fp+1], ah, bl[2], bl[3]);
                mma16816(acc[2*fp],   al, bh[0], bh[1]);
                mma16816(acc[2*fp+1], al, bh[2], bh[3]);
            }
        }
    }
    __syncthreads();

    // asum[b][k]
    if (t < 64) {
        float s = 0.f;
#pragma unroll
        for (int p = 0; p < 8; p++) s += g_asum_part[(bIdx * 8 + p) * 64 + t];
        s_asum[t] = s;
    }
    __syncthreads();

    // epilogue: v = acc + asum[k]*C[d,k]; write g_v; per-k sumsq partials
    const int q = l >> 2, qq = l & 3;
    const int dg0 = d0 + 16 * wid + q;
    float sq[8][2];
#pragma unroll
    for (int f = 0; f < 8; f++) {
        const int k0 = 8 * f + 2 * qq;
        float as0 = s_asum[k0], as1 = s_asum[k0 + 1];
        float2 c0 = *(const float2*)(Cm + (size_t)dg0 * K_ + k0);
        float2 c1 = *(const float2*)(Cm + (size_t)(dg0 + 8) * K_ + k0);
        float v00 = acc[f][0] + as0 * c0.x, v01 = acc[f][1] + as1 * c0.y;
        float v10 = acc[f][2] + as0 * c1.x, v11 = acc[f][3] + as1 * c1.y;
        *(float2*)(g_v + ((size_t)bIdx * D_ + dg0) * K_ + k0)     = make_float2(v00, v01);
        *(float2*)(g_v + ((size_t)bIdx * D_ + dg0 + 8) * K_ + k0) = make_float2(v10, v11);
        sq[f][0] = v00 * v00 + v10 * v10;
        sq[f][1] = v01 * v01 + v11 * v11;
    }
#pragma unroll
    for (int f = 0; f < 8; f++)
#pragma unroll
        for (int j = 0; j < 2; j++) {
            float v = sq[f][j];
            v += __shfl_xor_sync(~0u, v, 4);
            v += __shfl_xor_sync(~0u, v, 8);
            v += __shfl_xor_sync(~0u, v, 16);
            sq[f][j] = v;
        }
    if (l < 4) {
#pragma unroll
        for (int f = 0; f < 8; f++) {
            s_red[wid * 64 + 8 * f + 2 * l]     = sq[f][0];
            s_red[wid * 64 + 8 * f + 2 * l + 1] = sq[f][1];
        }
    }
    __syncthreads();
    if (t < 64) {
        float S = 0.f;
#pragma unroll
        for (int w8 = 0; w8 < 8; w8++) S += s_red[w8 * 64 + t];
        g_S_part[(bIdx * 4 + blockIdx.x) * 64 + t] = S;
    }
}

// ---------------- kernel 3: per-batch norms ----------------
__global__ void normc_kernel() {   // 64 blocks x 64 threads
    __shared__ float sS[64];
    const int b = blockIdx.x, t = threadIdx.x;
    float s = g_S_part[(b * 4 + 0) * 64 + t] + g_S_part[(b * 4 + 1) * 64 + t]
            + g_S_part[(b * 4 + 2) * 64 + t] + g_S_part[(b * 4 + 3) * 64 + t];
    sS[t] = s;
    g_invrow[b * 64 + t] = rsqrtf(s + EPS_);
    __syncthreads();
    if (t == 0) {
        float g = 0.f;
#pragma unroll
        for (int i = 0; i < 64; i++) g += sS[i] / (sS[i] + EPS_);
        g_ginv[b] = rsqrtf(g + EPS_);
    }
}

// ---------------- kernel 4: final scale (streaming) ----------------
__global__ __launch_bounds__(256) void scale_kernel(float* __restrict__ out) {
    __shared__ float sInv[64];
    __shared__ float sG;
    const int b = blockIdx.x >> 3, seg = blockIdx.x & 7, t = threadIdx.x;
    if (t < 64) sInv[t] = g_invrow[b * 64 + t];
    if (t == 0) sG = g_ginv[b];
    __syncthreads();
    const float gg = sG;
    const float4* vb = (const float4*)(g_v + (size_t)b * D_ * K_);
    float4* ob = (float4*)(out + (size_t)b * D_ * K_);
#pragma unroll
    for (int i = 0; i < 4; i++) {
        int e4 = seg * 1024 + t + i * 256;
        float4 v = vb[e4];
        int k = (e4 & 15) * 4;
        v.x *= sInv[k] * gg; v.y *= sInv[k + 1] * gg;
        v.z *= sInv[k + 2] * gg; v.w *= sInv[k + 3] * gg;
        ob[e4] = v;
    }
}

// ---------------------------------------------------------------------------
extern "C" void kernel_launch(void* const* d_in, const int* in_sizes, int n_in,
                              void* d_out, int out_size) {
    const float* x  = (const float*)d_in[0];   // [B,H,W,D]
    const float* w  = (const float*)d_in[1];   // [D,K]
    const float* Cm = (const float*)d_in[2];   // [D,K]
    float* out = (float*)d_out;                // [B, D*K]

    prep_kernel<<<128, 256>>>(w);
    gemm1_kernel<<<512, 256>>>(x);
    gemm2_kernel<<<dim3(4, B_), 256>>>(x, Cm);
    normc_kernel<<<64, 64>>>();
    scale_kernel<<<512, 256>>>(out);
}

// round 4
// speedup vs baseline: 4.8016x; 1.8449x over previous
#include <cuda_runtime.h>
#include <cuda_fp16.h>
#include <stdint.h>
#include <math.h>

#define B_  64
#define N_  1024
#define D_  512
#define K_  64
#define EPS_ 1e-12f

// ---------------- scratch ----------------
__device__ __half g_wT[K_ * D_];                         // w^T fp16 [k][d]
__device__ __half g_aT[(size_t)B_ * K_ * N_];            // a^T fp16 [b][k][n]
__device__ float g_asum_part[B_ * 8 * K_];
__device__ float g_S_part[B_ * 4 * K_];
__device__ float g_v[(size_t)B_ * D_ * K_];              // v pre-norm [b][d][k]

// ---------------- helpers ----------------
__device__ __forceinline__ uint32_t smem_u32(const void* p) {
    uint32_t a;
    asm("{ .reg .u64 t; cvta.to.shared.u64 t, %1; cvt.u32.u64 %0, t; }" : "=r"(a) : "l"(p));
    return a;
}
__device__ __forceinline__ uint32_t sw128(uint32_t off) { return off ^ ((off >> 3) & 0x70); }
__device__ __forceinline__ uint32_t sw256(uint32_t off) { return off ^ ((off >> 4) & 0x70); }

__device__ __forceinline__ void ldsm_x4(uint32_t* r, uint32_t a) {
    asm volatile("ldmatrix.sync.aligned.m8n8.x4.shared.b16 {%0,%1,%2,%3}, [%4];"
        : "=r"(r[0]), "=r"(r[1]), "=r"(r[2]), "=r"(r[3]) : "r"(a));
}
__device__ __forceinline__ void ldsm_x4t(uint32_t* r, uint32_t a) {
    asm volatile("ldmatrix.sync.aligned.m8n8.x4.trans.shared.b16 {%0,%1,%2,%3}, [%4];"
        : "=r"(r[0]), "=r"(r[1]), "=r"(r[2]), "=r"(r[3]) : "r"(a));
}
__device__ __forceinline__ void mma16816(float* c, const uint32_t* a, uint32_t b0, uint32_t b1) {
    asm volatile("mma.sync.aligned.m16n8k16.row.col.f32.f16.f16.f32 "
        "{%0,%1,%2,%3}, {%4,%5,%6,%7}, {%8,%9}, {%0,%1,%2,%3};"
        : "+f"(c[0]), "+f"(c[1]), "+f"(c[2]), "+f"(c[3])
        : "r"(a[0]), "r"(a[1]), "r"(a[2]), "r"(a[3]), "r"(b0), "r"(b1));
}
__device__ __forceinline__ void sts64(uint32_t addr, uint32_t a, uint32_t b) {
    asm volatile("st.shared.v2.b32 [%0], {%1,%2};" :: "r"(addr), "r"(a), "r"(b) : "memory");
}
__device__ __forceinline__ void sts128(uint32_t addr, uint4 v) {
    asm volatile("st.shared.v4.b32 [%0], {%1,%2,%3,%4};"
        :: "r"(addr), "r"(v.x), "r"(v.y), "r"(v.z), "r"(v.w) : "memory");
}
__device__ __forceinline__ uint32_t h2(float a, float b) {
    __half2 h = __floats2half2_rn(a, b);
    return *(uint32_t*)&h;
}

// ---------------- kernel 0: w -> wT fp16 ----------------
__global__ __launch_bounds__(256) void prep_kernel(const float* __restrict__ w) {
    int e = blockIdx.x * 256 + threadIdx.x;        // 32768 elems
    int k = e >> 9, d = e & 511;
    g_wT[(size_t)k * D_ + d] = __float2half(w[(size_t)d * K_ + k]);
}

// ---------------- kernel 1: s = x@w (fp16 HMMA) + softmax -> aT ----------------
// CTA: 128 n-rows x 64 k-cols; 8 warps x (16x64); 8 d-chunks, double-buffered
__global__ __launch_bounds__(256) void gemm1_kernel(const float* __restrict__ x) {
    __shared__ __align__(1024) char smem[49152];
    const uint32_t S0 = smem_u32(smem);
    // buffers: X[buf] 16KB, W[buf] 8KB : buf0 @0/16384, buf1 @24576/40960
    float* stage = (float*)smem;                   // overlay post-loop: 128x66 f32

    const int t = threadIdx.x, wid = t >> 5, l = t & 31;
    const int bIdx = blockIdx.x >> 3, tile = blockIdx.x & 7;
    const float* xb = x + ((size_t)bIdx * N_ + (size_t)tile * 128) * D_;

    float acc[8][4];
#pragma unroll
    for (int f = 0; f < 8; f++)
#pragma unroll
        for (int j = 0; j < 4; j++) acc[f][j] = 0.f;

    const int rA  = (l & 15);
    const int cA8 = (l >> 4) << 3;
    const int rB  = (l & 7) + ((l >> 4) << 3);
    const int cB8 = ((l >> 3) & 1) << 3;

    float4 rx[8];
    uint4  rw[2];

    // ldg chunk c into regs
    auto ldg_chunk = [&](int c) {
        const int d0 = c * 64;
#pragma unroll
        for (int i = 0; i < 8; i++) {
            int e = t + i * 256, r = e >> 4, f4 = e & 15;
            rx[i] = *(const float4*)(xb + (size_t)r * D_ + d0 + f4 * 4);
        }
#pragma unroll
        for (int i = 0; i < 2; i++) {
            int e = t + i * 256, r = e >> 3, u = e & 7;
            rw[i] = *(const uint4*)((const char*)g_wT + ((size_t)r * D_ + d0) * 2 + u * 16);
        }
    };
    auto sts_chunk = [&](int buf) {
        const uint32_t XH = S0 + buf * 24576, WH = XH + 16384;
#pragma unroll
        for (int i = 0; i < 8; i++) {
            int e = t + i * 256, r = e >> 4, f4 = e & 15;
            sts64(XH + sw128((uint32_t)(r * 128 + f4 * 8)),
                  h2(rx[i].x, rx[i].y), h2(rx[i].z, rx[i].w));
        }
#pragma unroll
        for (int i = 0; i < 2; i++) {
            int e = t + i * 256, r = e >> 3, u = e & 7;
            sts128(WH + sw128((uint32_t)(r * 128 + u * 16)), rw[i]);
        }
    };

    ldg_chunk(0);
    sts_chunk(0);
    __syncthreads();

#pragma unroll
    for (int c = 0; c < 8; c++) {
        if (c < 7) ldg_chunk(c + 1);
        const uint32_t XH = S0 + (c & 1) * 24576, WH = XH + 16384;
#pragma unroll
        for (int ks = 0; ks < 4; ks++) {
            const int k0 = ks * 16;
            uint32_t ah[4];
            ldsm_x4(ah, XH + sw128((uint32_t)((16 * wid + rA) * 128 + (k0 + cA8) * 2)));
#pragma unroll
            for (int fp = 0; fp < 4; fp++) {
                uint32_t bh[4];
                ldsm_x4(bh, WH + sw128((uint32_t)((fp * 16 + rB) * 128 + (k0 + cB8) * 2)));
                mma16816(acc[2*fp],   ah, bh[0], bh[1]);
                mma16816(acc[2*fp+1], ah, bh[2], bh[3]);
            }
        }
        if (c < 7) {
            sts_chunk((c + 1) & 1);
            __syncthreads();
        }
    }
    __syncthreads();

    // softmax (rows r0 = 16*wid + l/4 and r0+8; full row lives in the 4-lane quad)
    const int q = l >> 2, qq = l & 3;
    const int r0 = 16 * wid + q;
    float m0 = -1e30f, m1 = -1e30f;
#pragma unroll
    for (int f = 0; f < 8; f++) {
        m0 = fmaxf(m0, fmaxf(acc[f][0], acc[f][1]));
        m1 = fmaxf(m1, fmaxf(acc[f][2], acc[f][3]));
    }
    m0 = fmaxf(m0, __shfl_xor_sync(~0u, m0, 1));
    m0 = fmaxf(m0, __shfl_xor_sync(~0u, m0, 2));
    m1 = fmaxf(m1, __shfl_xor_sync(~0u, m1, 1));
    m1 = fmaxf(m1, __shfl_xor_sync(~0u, m1, 2));
    float s0 = 0.f, s1 = 0.f;
#pragma unroll
    for (int f = 0; f < 8; f++) {
        acc[f][0] = __expf(acc[f][0] - m0);
        acc[f][1] = __expf(acc[f][1] - m0);
        acc[f][2] = __expf(acc[f][2] - m1);
        acc[f][3] = __expf(acc[f][3] - m1);
        s0 += acc[f][0] + acc[f][1];
        s1 += acc[f][2] + acc[f][3];
    }
    s0 += __shfl_xor_sync(~0u, s0, 1); s0 += __shfl_xor_sync(~0u, s0, 2);
    s1 += __shfl_xor_sync(~0u, s1, 1); s1 += __shfl_xor_sync(~0u, s1, 2);
    const float i0 = 1.0f / s0, i1 = 1.0f / s1;
#pragma unroll
    for (int f = 0; f < 8; f++) {
        *(float2*)&stage[r0 * 66 + 8 * f + 2 * qq]       = make_float2(acc[f][0] * i0, acc[f][1] * i0);
        *(float2*)&stage[(r0 + 8) * 66 + 8 * f + 2 * qq] = make_float2(acc[f][2] * i1, acc[f][3] * i1);
    }
    __syncthreads();

    // asum partial over this 128-row tile
    if (t < 64) {
        float s = 0.f;
#pragma unroll 8
        for (int r = 0; r < 128; r++) s += stage[r * 66 + t];
        g_asum_part[(bIdx * 8 + tile) * 64 + t] = s;
    }
    // aT fp16 (transpose through stage)
    const size_t abase = (size_t)bIdx * K_ * N_ + (size_t)tile * 128;
    for (int e = t; e < 64 * 128; e += 256) {
        int k = e >> 7, j = e & 127;
        g_aT[abase + (size_t)k * N_ + j] = __float2half(stage[j * 66 + k]);
    }
}

// ---------------- kernel 2: vT[d,k] = sum_n x[n,d]*a[n,k] (fp16 HMMA, trans-A) ----
// CTA: 128 d-rows x 64 k-cols per (d-tile, b); 16 n-chunks, double-buffered
__global__ __launch_bounds__(256) void gemm2_kernel(const float* __restrict__ x,
                                                    const float* __restrict__ Cm) {
    __shared__ __align__(1024) char smem[49152];
    const uint32_t S0 = smem_u32(smem);
    // buffers: XS[buf] 16KB, AT[buf] 8KB : buf0 @0/16384, buf1 @24576/40960
    float* s_red  = (float*)smem;          // overlay post-loop: 8*64 floats
    float* s_asum = (float*)(smem + 2048); // overlay post-loop: 64 floats

    const int t = threadIdx.x, wid = t >> 5, l = t & 31;
    const int bIdx = blockIdx.y, d0 = blockIdx.x * 128;
    const float* xb = x + (size_t)bIdx * N_ * D_ + d0;
    const __half* ath = g_aT + (size_t)bIdx * K_ * N_;

    float acc[8][4];
#pragma unroll
    for (int f = 0; f < 8; f++)
#pragma unroll
        for (int j = 0; j < 4; j++) acc[f][j] = 0.f;

    const int rT = (l & 7) + ((l >> 4) << 3);
    const int c8 = ((l >> 3) & 1) << 3;

    float4 rx[8];
    uint4  rb[2];

    auto ldg_chunk = [&](int c) {
        const int n0 = c * 64;
#pragma unroll
        for (int i = 0; i < 8; i++) {
            int e = t + i * 256, r = e >> 5, f4 = e & 31;
            rx[i] = *(const float4*)(xb + (size_t)(n0 + r) * D_ + f4 * 4);
        }
#pragma unroll
        for (int i = 0; i < 2; i++) {
            int e = t + i * 256, r = e >> 3, u = e & 7;
            rb[i] = *(const uint4*)((const char*)(ath + (size_t)r * N_ + n0) + u * 16);
        }
    };
    auto sts_chunk = [&](int buf) {
        const uint32_t XS = S0 + buf * 24576, AT = XS + 16384;
#pragma unroll
        for (int i = 0; i < 8; i++) {
            int e = t + i * 256, r = e >> 5, f4 = e & 31;
            sts64(XS + sw256((uint32_t)(r * 256 + f4 * 8)),
                  h2(rx[i].x, rx[i].y), h2(rx[i].z, rx[i].w));
        }
#pragma unroll
        for (int i = 0; i < 2; i++) {
            int e = t + i * 256, r = e >> 3, u = e & 7;
            sts128(AT + sw128((uint32_t)(r * 128 + u * 16)), rb[i]);
        }
    };

    ldg_chunk(0);
    sts_chunk(0);
    __syncthreads();

#pragma unroll 1
    for (int c = 0; c < 16; c++) {
        if (c < 15) ldg_chunk(c + 1);
        const uint32_t XS = S0 + (c & 1) * 24576, AT = XS + 16384;
#pragma unroll
        for (int ks = 0; ks < 4; ks++) {
            const int nk = ks * 16;
            uint32_t ah[4];
            ldsm_x4t(ah, XS + sw256((uint32_t)((nk + rT) * 256 + (16 * wid + c8) * 2)));
#pragma unroll
            for (int fp = 0; fp < 4; fp++) {
                uint32_t bh[4];
                ldsm_x4(bh, AT + sw128((uint32_t)((fp * 16 + rT) * 128 + (nk + c8) * 2)));
                mma16816(acc[2*fp],   ah, bh[0], bh[1]);
                mma16816(acc[2*fp+1], ah, bh[2], bh[3]);
            }
        }
        if (c < 15) {
            sts_chunk((c + 1) & 1);
            __syncthreads();
        }
    }
    __syncthreads();

    // asum[b][k]
    if (t < 64) {
        float s = 0.f;
#pragma unroll
        for (int p = 0; p < 8; p++) s += g_asum_part[(bIdx * 8 + p) * 64 + t];
        s_asum[t] = s;
    }
    __syncthreads();

    // epilogue: v = acc + asum[k]*C[d,k]; write g_v; per-k sumsq partials
    const int q = l >> 2, qq = l & 3;
    const int dg0 = d0 + 16 * wid + q;
    float sq[8][2];
#pragma unroll
    for (int f = 0; f < 8; f++) {
        const int k0 = 8 * f + 2 * qq;
        float as0 = s_asum[k0], as1 = s_asum[k0 + 1];
        float2 c0 = *(const float2*)(Cm + (size_t)dg0 * K_ + k0);
        float2 c1 = *(const float2*)(Cm + (size_t)(dg0 + 8) * K_ + k0);
        float v00 = acc[f][0] + as0 * c0.x, v01 = acc[f][1] + as1 * c0.y;
        float v10 = acc[f][2] + as0 * c1.x, v11 = acc[f][3] + as1 * c1.y;
        *(float2*)(g_v + ((size_t)bIdx * D_ + dg0) * K_ + k0)     = make_float2(v00, v01);
        *(float2*)(g_v + ((size_t)bIdx * D_ + dg0 + 8) * K_ + k0) = make_float2(v10, v11);
        sq[f][0] = v00 * v00 + v10 * v10;
        sq[f][1] = v01 * v01 + v11 * v11;
    }
#pragma unroll
    for (int f = 0; f < 8; f++)
#pragma unroll
        for (int j = 0; j < 2; j++) {
            float v = sq[f][j];
            v += __shfl_xor_sync(~0u, v, 4);
            v += __shfl_xor_sync(~0u, v, 8);
            v += __shfl_xor_sync(~0u, v, 16);
            sq[f][j] = v;
        }
    if (l < 4) {
#pragma unroll
        for (int f = 0; f < 8; f++) {
            s_red[wid * 64 + 8 * f + 2 * l]     = sq[f][0];
            s_red[wid * 64 + 8 * f + 2 * l + 1] = sq[f][1];
        }
    }
    __syncthreads();
    if (t < 64) {
        float S = 0.f;
#pragma unroll
        for (int w8 = 0; w8 < 8; w8++) S += s_red[w8 * 64 + t];
        g_S_part[(bIdx * 4 + blockIdx.x) * 64 + t] = S;
    }
}

// ---------------- kernel 3: fused norms + final scale ----------------
__global__ __launch_bounds__(256) void scale_kernel(float* __restrict__ out) {
    __shared__ float sS[64];
    __shared__ float sInv[64];
    __shared__ float sG;
    const int b = blockIdx.x >> 3, seg = blockIdx.x & 7, t = threadIdx.x;
    if (t < 64) {
        float s = g_S_part[(b * 4 + 0) * 64 + t] + g_S_part[(b * 4 + 1) * 64 + t]
                + g_S_part[(b * 4 + 2) * 64 + t] + g_S_part[(b * 4 + 3) * 64 + t];
        sS[t] = s;
        sInv[t] = rsqrtf(s + EPS_);
    }
    __syncthreads();
    if (t < 32) {
        float a0 = sS[t], a1 = sS[t + 32];
        float g = a0 / (a0 + EPS_) + a1 / (a1 + EPS_);
#pragma unroll
        for (int off = 16; off; off >>= 1) g += __shfl_xor_sync(~0u, g, off);
        if (t == 0) sG = rsqrtf(g + EPS_);
    }
    __syncthreads();
    const float gg = sG;
    const float4* vb = (const float4*)(g_v + (size_t)b * D_ * K_);
    float4* ob = (float4*)(out + (size_t)b * D_ * K_);
#pragma unroll
    for (int i = 0; i < 4; i++) {
        int e4 = seg * 1024 + t + i * 256;
        float4 v = vb[e4];
        int k = (e4 & 15) * 4;
        v.x *= sInv[k] * gg; v.y *= sInv[k + 1] * gg;
        v.z *= sInv[k + 2] * gg; v.w *= sInv[k + 3] * gg;
        ob[e4] = v;
    }
}

// ---------------------------------------------------------------------------
extern "C" void kernel_launch(void* const* d_in, const int* in_sizes, int n_in,
                              void* d_out, int out_size) {
    const float* x  = (const float*)d_in[0];   // [B,H,W,D]
    const float* w  = (const float*)d_in[1];   // [D,K]
    const float* Cm = (const float*)d_in[2];   // [D,K]
    float* out = (float*)d_out;                // [B, D*K]

    prep_kernel<<<128, 256>>>(w);
    gemm1_kernel<<<512, 256>>>(x);
    gemm2_kernel<<<dim3(4, B_), 256>>>(x, Cm);
    scale_kernel<<<512, 256>>>(out);
}